// round 11
// baseline (speedup 1.0000x reference)
#include <cuda_runtime.h>
#include <math.h>

// Problem constants
#define EMB   1024
#define HS    64
#define BB    4
#define TT    4096
#define NROWS (BB * TT)   // 16384

// Scratch for projected q, k, v (fp32) — device globals (no allocations allowed)
__device__ float g_q[NROWS * HS];
__device__ float g_k[NROWS * HS];
__device__ float g_v[NROWS * HS];

// ---------------------------------------------------------------------------
// Fused projection kernel: q = x@Wq, k = x@Wk, v = x@Wv
// Reads each x row once, produces all three projections.
// grid = NROWS/64 = 256 blocks, 256 threads. BM=64, BN=64 (full head), BK=32.
// Thread micro-tile: 4 rows x 4 cols per output matrix (48 accumulators).
// ---------------------------------------------------------------------------
__global__ __launch_bounds__(256) void proj_kernel(
    const float* __restrict__ x,
    const float* __restrict__ Wq,
    const float* __restrict__ Wk,
    const float* __restrict__ Wv)
{
    __shared__ float Xs[64][33];        // padded: conflict-free row reads
    __shared__ float Ws[3][32][64];

    const int tid = threadIdx.x;
    const int tx  = tid & 15;           // output-col group (16)
    const int ty  = tid >> 4;           // output-row group (16)
    const int row0 = blockIdx.x * 64;

    float acc[3][4][4];
#pragma unroll
    for (int m = 0; m < 3; m++)
#pragma unroll
        for (int i = 0; i < 4; i++)
#pragma unroll
            for (int j = 0; j < 4; j++) acc[m][i][j] = 0.0f;

    const float* Wp[3] = {Wq, Wk, Wv};

    for (int k0 = 0; k0 < EMB; k0 += 32) {
        // X tile 64x32 = 512 float4 (2 per thread), coalesced
#pragma unroll
        for (int l = 0; l < 2; l++) {
            int idx = tid + l * 256;            // 0..511
            int r   = idx >> 3;                 // 8 float4 per row
            int c4  = idx & 7;
            float4 v = *(const float4*)(&x[(size_t)(row0 + r) * EMB + k0 + c4 * 4]);
            Xs[r][c4 * 4 + 0] = v.x;
            Xs[r][c4 * 4 + 1] = v.y;
            Xs[r][c4 * 4 + 2] = v.z;
            Xs[r][c4 * 4 + 3] = v.w;
        }
        // W tiles: 3 x (32x64) = 3 x 512 float4
#pragma unroll
        for (int m = 0; m < 3; m++) {
#pragma unroll
            for (int l = 0; l < 2; l++) {
                int idx = tid + l * 256;
                int r   = idx >> 4;             // 16 float4 per row
                int c4  = idx & 15;
                float4 v = *(const float4*)(&Wp[m][(size_t)(k0 + r) * HS + c4 * 4]);
                *(float4*)(&Ws[m][r][c4 * 4]) = v;
            }
        }
        __syncthreads();

#pragma unroll
        for (int kk = 0; kk < 32; kk++) {
            float xv[4];
#pragma unroll
            for (int i = 0; i < 4; i++) xv[i] = Xs[ty * 4 + i][kk];
#pragma unroll
            for (int m = 0; m < 3; m++) {
                float wv[4];
#pragma unroll
                for (int j = 0; j < 4; j++) wv[j] = Ws[m][kk][tx * 4 + j];
#pragma unroll
                for (int i = 0; i < 4; i++)
#pragma unroll
                    for (int j = 0; j < 4; j++)
                        acc[m][i][j] += xv[i] * wv[j];
            }
        }
        __syncthreads();
    }

#pragma unroll
    for (int i = 0; i < 4; i++) {
        size_t r = (size_t)(row0 + ty * 4 + i) * HS + tx * 4;
#pragma unroll
        for (int j = 0; j < 4; j++) g_q[r + j] = acc[0][i][j];
#pragma unroll
        for (int j = 0; j < 4; j++) g_k[r + j] = acc[1][i][j];
#pragma unroll
        for (int j = 0; j < 4; j++) g_v[r + j] = acc[2][i][j];
    }
}

// ---------------------------------------------------------------------------
// Flash-attention kernel (causal), fp32.
// grid = (T/64, B), 256 threads. BM = BN = 64, D = 64.
// Online softmax: running max m[i], running sum l[i] per query row.
// Smem: Qs[64][65], KP[64][65] (K tile, reused for P), Vs[64][65] -> 49920 B.
// ---------------------------------------------------------------------------
__global__ __launch_bounds__(256) void attn_kernel(float* __restrict__ out)
{
    extern __shared__ float sm[];
    float* Qs = sm;                 // 64*65
    float* KP = sm + 64 * 65;       // 64*65 (K, then P)
    float* Vs = sm + 2 * 64 * 65;   // 64*65

    const int tid = threadIdx.x;
    const int tx  = tid & 15;
    const int ty  = tid >> 4;
    const int b   = blockIdx.y;
    const int i0  = blockIdx.x * 64;                 // query tile start
    const size_t base = (size_t)b * TT * HS;

    // Load Q tile, folding in scale = EMB^-0.5 = 1/32 (exact power of two)
    const float sc = 0.03125f;
#pragma unroll
    for (int l = 0; l < 4; l++) {
        int idx = tid + l * 256;                     // 64 rows * 16 float4
        int r   = idx >> 4;
        int c4  = idx & 15;
        float4 v = *(const float4*)(&g_q[base + (size_t)(i0 + r) * HS + c4 * 4]);
        Qs[r * 65 + c4 * 4 + 0] = v.x * sc;
        Qs[r * 65 + c4 * 4 + 1] = v.y * sc;
        Qs[r * 65 + c4 * 4 + 2] = v.z * sc;
        Qs[r * 65 + c4 * 4 + 3] = v.w * sc;
    }

    float m[4], lsum[4], acc[4][4];
#pragma unroll
    for (int i = 0; i < 4; i++) { m[i] = -1e30f; lsum[i] = 0.0f; }
#pragma unroll
    for (int i = 0; i < 4; i++)
#pragma unroll
        for (int j = 0; j < 4; j++) acc[i][j] = 0.0f;

    for (int j0 = 0; j0 <= i0; j0 += 64) {
        __syncthreads();   // previous iteration's PV reads of KP/Vs complete

        // Load K, V tiles (coalesced float4 from global, scalar stores to padded smem)
#pragma unroll
        for (int l = 0; l < 4; l++) {
            int idx = tid + l * 256;
            int r   = idx >> 4;
            int c4  = idx & 15;
            float4 kv = *(const float4*)(&g_k[base + (size_t)(j0 + r) * HS + c4 * 4]);
            KP[r * 65 + c4 * 4 + 0] = kv.x;
            KP[r * 65 + c4 * 4 + 1] = kv.y;
            KP[r * 65 + c4 * 4 + 2] = kv.z;
            KP[r * 65 + c4 * 4 + 3] = kv.w;
            float4 vv = *(const float4*)(&g_v[base + (size_t)(j0 + r) * HS + c4 * 4]);
            Vs[r * 65 + c4 * 4 + 0] = vv.x;
            Vs[r * 65 + c4 * 4 + 1] = vv.y;
            Vs[r * 65 + c4 * 4 + 2] = vv.z;
            Vs[r * 65 + c4 * 4 + 3] = vv.w;
        }
        __syncthreads();

        // S = Q * K^T  (thread owns rows ty*4.., cols tx*4..)
        float s[4][4];
#pragma unroll
        for (int i = 0; i < 4; i++)
#pragma unroll
            for (int j = 0; j < 4; j++) s[i][j] = 0.0f;

#pragma unroll 8
        for (int kk = 0; kk < 64; kk++) {
            float qv[4], kv[4];
#pragma unroll
            for (int i = 0; i < 4; i++) qv[i] = Qs[(ty * 4 + i) * 65 + kk];
#pragma unroll
            for (int j = 0; j < 4; j++) kv[j] = KP[(tx * 4 + j) * 65 + kk];
#pragma unroll
            for (int i = 0; i < 4; i++)
#pragma unroll
                for (int j = 0; j < 4; j++) s[i][j] += qv[i] * kv[j];
        }

        // Causal mask (only the diagonal tile needs it)
        if (j0 == i0) {
#pragma unroll
            for (int i = 0; i < 4; i++) {
                int qidx = ty * 4 + i;
#pragma unroll
                for (int j = 0; j < 4; j++) {
                    if (tx * 4 + j > qidx) s[i][j] = -1e30f;
                }
            }
        }

        // Online softmax per row (row spans 16 consecutive lanes -> shfl width 16)
#pragma unroll
        for (int i = 0; i < 4; i++) {
            float mloc = fmaxf(fmaxf(s[i][0], s[i][1]), fmaxf(s[i][2], s[i][3]));
#pragma unroll
            for (int off = 8; off >= 1; off >>= 1)
                mloc = fmaxf(mloc, __shfl_xor_sync(0xffffffffu, mloc, off, 16));
            float mnew = fmaxf(m[i], mloc);
            float corr = __expf(m[i] - mnew);
            m[i] = mnew;

            float psum = 0.0f;
#pragma unroll
            for (int j = 0; j < 4; j++) {
                float p = __expf(s[i][j] - mnew);   // masked -1e30 underflows to 0
                s[i][j] = p;
                psum += p;
            }
#pragma unroll
            for (int off = 8; off >= 1; off >>= 1)
                psum += __shfl_xor_sync(0xffffffffu, psum, off, 16);

            lsum[i] = lsum[i] * corr + psum;
#pragma unroll
            for (int j = 0; j < 4; j++) acc[i][j] *= corr;
        }

        __syncthreads();   // all warps done reading K from KP

        // Write P into KP (same [row][65] layout)
#pragma unroll
        for (int i = 0; i < 4; i++)
#pragma unroll
            for (int j = 0; j < 4; j++)
                KP[(ty * 4 + i) * 65 + tx * 4 + j] = s[i][j];
        __syncthreads();

        // O += P @ V   (contraction over key index ss)
#pragma unroll 8
        for (int ss = 0; ss < 64; ss++) {
            float pv[4], vv[4];
#pragma unroll
            for (int i = 0; i < 4; i++) pv[i] = KP[(ty * 4 + i) * 65 + ss];
#pragma unroll
            for (int j = 0; j < 4; j++) vv[j] = Vs[ss * 65 + tx * 4 + j];
#pragma unroll
            for (int i = 0; i < 4; i++)
#pragma unroll
                for (int j = 0; j < 4; j++) acc[i][j] += pv[i] * vv[j];
        }
    }

    // Epilogue: out = acc / l
#pragma unroll
    for (int i = 0; i < 4; i++) {
        float inv = 1.0f / lsum[i];
        size_t r = base + (size_t)(i0 + ty * 4 + i) * HS + tx * 4;
#pragma unroll
        for (int j = 0; j < 4; j++) out[r + j] = acc[i][j] * inv;
    }
}

// ---------------------------------------------------------------------------
// kernel_launch: proj -> attention. Graph-capturable, allocation-free.
// Inputs (metadata order): x [B,T,E], Wq [E,H], Wk [E,H], Wv [E,H], all fp32.
// Output: [B,T,H] fp32.
// ---------------------------------------------------------------------------
extern "C" void kernel_launch(void* const* d_in, const int* in_sizes, int n_in,
                              void* d_out, int out_size)
{
    const float* x  = (const float*)d_in[0];
    const float* Wq = (const float*)d_in[1];
    const float* Wk = (const float*)d_in[2];
    const float* Wv = (const float*)d_in[3];
    float* out = (float*)d_out;

    proj_kernel<<<NROWS / 64, 256>>>(x, Wq, Wk, Wv);

    const int smem = 3 * 64 * 65 * (int)sizeof(float);   // 49920 B > 48K default
    cudaFuncSetAttribute(attn_kernel, cudaFuncAttributeMaxDynamicSharedMemorySize, smem);
    attn_kernel<<<dim3(TT / 64, BB), 256, smem>>>(out);
}

// round 12
// speedup vs baseline: 1.0022x; 1.0022x over previous
#include <cuda_runtime.h>
#include <math.h>

// Problem constants
#define EMB   1024
#define HS    64
#define BB    4
#define TT    4096
#define NROWS (BB * TT)   // 16384

// Scratch for projected q, k, v (fp32) — device globals (no allocations allowed)
__device__ float g_q[NROWS * HS];
__device__ float g_k[NROWS * HS];
__device__ float g_v[NROWS * HS];

// ---------------------------------------------------------------------------
// Fused projection kernel: q = x@Wq, k = x@Wk, v = x@Wv
// Reads each x row once, produces all three projections.
// grid = NROWS/64 = 256 blocks, 256 threads. BM=64, BN=64 (full head), BK=32.
// Thread micro-tile: 4 rows x 4 cols per output matrix (48 accumulators).
// ---------------------------------------------------------------------------
__global__ __launch_bounds__(256) void proj_kernel(
    const float* __restrict__ x,
    const float* __restrict__ Wq,
    const float* __restrict__ Wk,
    const float* __restrict__ Wv)
{
    __shared__ float Xs[64][33];        // padded: conflict-free row reads
    __shared__ float Ws[3][32][64];

    const int tid = threadIdx.x;
    const int tx  = tid & 15;           // output-col group (16)
    const int ty  = tid >> 4;           // output-row group (16)
    const int row0 = blockIdx.x * 64;

    float acc[3][4][4];
#pragma unroll
    for (int m = 0; m < 3; m++)
#pragma unroll
        for (int i = 0; i < 4; i++)
#pragma unroll
            for (int j = 0; j < 4; j++) acc[m][i][j] = 0.0f;

    const float* Wp[3] = {Wq, Wk, Wv};

    for (int k0 = 0; k0 < EMB; k0 += 32) {
        // X tile 64x32 = 512 float4 (2 per thread), coalesced
#pragma unroll
        for (int l = 0; l < 2; l++) {
            int idx = tid + l * 256;            // 0..511
            int r   = idx >> 3;                 // 8 float4 per row
            int c4  = idx & 7;
            float4 v = *(const float4*)(&x[(size_t)(row0 + r) * EMB + k0 + c4 * 4]);
            Xs[r][c4 * 4 + 0] = v.x;
            Xs[r][c4 * 4 + 1] = v.y;
            Xs[r][c4 * 4 + 2] = v.z;
            Xs[r][c4 * 4 + 3] = v.w;
        }
        // W tiles: 3 x (32x64) = 3 x 512 float4
#pragma unroll
        for (int m = 0; m < 3; m++) {
#pragma unroll
            for (int l = 0; l < 2; l++) {
                int idx = tid + l * 256;
                int r   = idx >> 4;             // 16 float4 per row
                int c4  = idx & 15;
                float4 v = *(const float4*)(&Wp[m][(size_t)(k0 + r) * HS + c4 * 4]);
                *(float4*)(&Ws[m][r][c4 * 4]) = v;
            }
        }
        __syncthreads();

#pragma unroll
        for (int kk = 0; kk < 32; kk++) {
            float xv[4];
#pragma unroll
            for (int i = 0; i < 4; i++) xv[i] = Xs[ty * 4 + i][kk];
#pragma unroll
            for (int m = 0; m < 3; m++) {
                float wv[4];
#pragma unroll
                for (int j = 0; j < 4; j++) wv[j] = Ws[m][kk][tx * 4 + j];
#pragma unroll
                for (int i = 0; i < 4; i++)
#pragma unroll
                    for (int j = 0; j < 4; j++)
                        acc[m][i][j] += xv[i] * wv[j];
            }
        }
        __syncthreads();
    }

#pragma unroll
    for (int i = 0; i < 4; i++) {
        size_t r = (size_t)(row0 + ty * 4 + i) * HS + tx * 4;
#pragma unroll
        for (int j = 0; j < 4; j++) g_q[r + j] = acc[0][i][j];
#pragma unroll
        for (int j = 0; j < 4; j++) g_k[r + j] = acc[1][i][j];
#pragma unroll
        for (int j = 0; j < 4; j++) g_v[r + j] = acc[2][i][j];
    }
}

// ---------------------------------------------------------------------------
// Flash-attention kernel (causal), fp32.
// grid = (T/64, B), 256 threads. BM = BN = 64, D = 64.
// Online softmax: running max m[i], running sum l[i] per query row.
// Smem: Qs[64][65], KP[64][65] (K tile, reused for P), Vs[64][65] -> 49920 B.
// ---------------------------------------------------------------------------
__global__ __launch_bounds__(256) void attn_kernel(float* __restrict__ out)
{
    extern __shared__ float sm[];
    float* Qs = sm;                 // 64*65
    float* KP = sm + 64 * 65;       // 64*65 (K, then P)
    float* Vs = sm + 2 * 64 * 65;   // 64*65

    const int tid = threadIdx.x;
    const int tx  = tid & 15;
    const int ty  = tid >> 4;
    const int b   = blockIdx.y;
    const int i0  = blockIdx.x * 64;                 // query tile start
    const size_t base = (size_t)b * TT * HS;

    // Load Q tile, folding in scale = EMB^-0.5 = 1/32 (exact power of two)
    const float sc = 0.03125f;
#pragma unroll
    for (int l = 0; l < 4; l++) {
        int idx = tid + l * 256;                     // 64 rows * 16 float4
        int r   = idx >> 4;
        int c4  = idx & 15;
        float4 v = *(const float4*)(&g_q[base + (size_t)(i0 + r) * HS + c4 * 4]);
        Qs[r * 65 + c4 * 4 + 0] = v.x * sc;
        Qs[r * 65 + c4 * 4 + 1] = v.y * sc;
        Qs[r * 65 + c4 * 4 + 2] = v.z * sc;
        Qs[r * 65 + c4 * 4 + 3] = v.w * sc;
    }

    float m[4], lsum[4], acc[4][4];
#pragma unroll
    for (int i = 0; i < 4; i++) { m[i] = -1e30f; lsum[i] = 0.0f; }
#pragma unroll
    for (int i = 0; i < 4; i++)
#pragma unroll
        for (int j = 0; j < 4; j++) acc[i][j] = 0.0f;

    for (int j0 = 0; j0 <= i0; j0 += 64) {
        __syncthreads();   // previous iteration's PV reads of KP/Vs complete

        // Load K, V tiles (coalesced float4 from global, scalar stores to padded smem)
#pragma unroll
        for (int l = 0; l < 4; l++) {
            int idx = tid + l * 256;
            int r   = idx >> 4;
            int c4  = idx & 15;
            float4 kv = *(const float4*)(&g_k[base + (size_t)(j0 + r) * HS + c4 * 4]);
            KP[r * 65 + c4 * 4 + 0] = kv.x;
            KP[r * 65 + c4 * 4 + 1] = kv.y;
            KP[r * 65 + c4 * 4 + 2] = kv.z;
            KP[r * 65 + c4 * 4 + 3] = kv.w;
            float4 vv = *(const float4*)(&g_v[base + (size_t)(j0 + r) * HS + c4 * 4]);
            Vs[r * 65 + c4 * 4 + 0] = vv.x;
            Vs[r * 65 + c4 * 4 + 1] = vv.y;
            Vs[r * 65 + c4 * 4 + 2] = vv.z;
            Vs[r * 65 + c4 * 4 + 3] = vv.w;
        }
        __syncthreads();

        // S = Q * K^T  (thread owns rows ty*4.., cols tx*4..)
        float s[4][4];
#pragma unroll
        for (int i = 0; i < 4; i++)
#pragma unroll
            for (int j = 0; j < 4; j++) s[i][j] = 0.0f;

#pragma unroll 8
        for (int kk = 0; kk < 64; kk++) {
            float qv[4], kv[4];
#pragma unroll
            for (int i = 0; i < 4; i++) qv[i] = Qs[(ty * 4 + i) * 65 + kk];
#pragma unroll
            for (int j = 0; j < 4; j++) kv[j] = KP[(tx * 4 + j) * 65 + kk];
#pragma unroll
            for (int i = 0; i < 4; i++)
#pragma unroll
                for (int j = 0; j < 4; j++) s[i][j] += qv[i] * kv[j];
        }

        // Causal mask (only the diagonal tile needs it)
        if (j0 == i0) {
#pragma unroll
            for (int i = 0; i < 4; i++) {
                int qidx = ty * 4 + i;
#pragma unroll
                for (int j = 0; j < 4; j++) {
                    if (tx * 4 + j > qidx) s[i][j] = -1e30f;
                }
            }
        }

        // Online softmax per row (row spans 16 consecutive lanes -> shfl width 16)
#pragma unroll
        for (int i = 0; i < 4; i++) {
            float mloc = fmaxf(fmaxf(s[i][0], s[i][1]), fmaxf(s[i][2], s[i][3]));
#pragma unroll
            for (int off = 8; off >= 1; off >>= 1)
                mloc = fmaxf(mloc, __shfl_xor_sync(0xffffffffu, mloc, off, 16));
            float mnew = fmaxf(m[i], mloc);
            float corr = __expf(m[i] - mnew);
            m[i] = mnew;

            float psum = 0.0f;
#pragma unroll
            for (int j = 0; j < 4; j++) {
                float p = __expf(s[i][j] - mnew);   // masked -1e30 underflows to 0
                s[i][j] = p;
                psum += p;
            }
#pragma unroll
            for (int off = 8; off >= 1; off >>= 1)
                psum += __shfl_xor_sync(0xffffffffu, psum, off, 16);

            lsum[i] = lsum[i] * corr + psum;
#pragma unroll
            for (int j = 0; j < 4; j++) acc[i][j] *= corr;
        }

        __syncthreads();   // all warps done reading K from KP

        // Write P into KP (same [row][65] layout)
#pragma unroll
        for (int i = 0; i < 4; i++)
#pragma unroll
            for (int j = 0; j < 4; j++)
                KP[(ty * 4 + i) * 65 + tx * 4 + j] = s[i][j];
        __syncthreads();

        // O += P @ V   (contraction over key index ss)
#pragma unroll 8
        for (int ss = 0; ss < 64; ss++) {
            float pv[4], vv[4];
#pragma unroll
            for (int i = 0; i < 4; i++) pv[i] = KP[(ty * 4 + i) * 65 + ss];
#pragma unroll
            for (int j = 0; j < 4; j++) vv[j] = Vs[ss * 65 + tx * 4 + j];
#pragma unroll
            for (int i = 0; i < 4; i++)
#pragma unroll
                for (int j = 0; j < 4; j++) acc[i][j] += pv[i] * vv[j];
        }
    }

    // Epilogue: out = acc / l
#pragma unroll
    for (int i = 0; i < 4; i++) {
        float inv = 1.0f / lsum[i];
        size_t r = base + (size_t)(i0 + ty * 4 + i) * HS + tx * 4;
#pragma unroll
        for (int j = 0; j < 4; j++) out[r + j] = acc[i][j] * inv;
    }
}

// ---------------------------------------------------------------------------
// kernel_launch: proj -> attention. Graph-capturable, allocation-free.
// Inputs (metadata order): x [B,T,E], Wq [E,H], Wk [E,H], Wv [E,H], all fp32.
// Output: [B,T,H] fp32.
// ---------------------------------------------------------------------------
extern "C" void kernel_launch(void* const* d_in, const int* in_sizes, int n_in,
                              void* d_out, int out_size)
{
    const float* x  = (const float*)d_in[0];
    const float* Wq = (const float*)d_in[1];
    const float* Wk = (const float*)d_in[2];
    const float* Wv = (const float*)d_in[3];
    float* out = (float*)d_out;

    proj_kernel<<<NROWS / 64, 256>>>(x, Wq, Wk, Wv);

    const int smem = 3 * 64 * 65 * (int)sizeof(float);   // 49920 B > 48K default
    cudaFuncSetAttribute(attn_kernel, cudaFuncAttributeMaxDynamicSharedMemorySize, smem);
    attn_kernel<<<dim3(TT / 64, BB), 256, smem>>>(out);
}